// round 6
// baseline (speedup 1.0000x reference)
#include <cuda_runtime.h>

#define NN 100000
#define NE 3000000
#define THIRD (NE/3)
#define NG 256
#define FIN 64
#define NH 32

#define GBN 128          // nodes per block in k_g
#define XPAD 68          // padded row stride (272B: 16B-aligned, conflict-free w/ np stride)

// ---- scratch (no allocations allowed) ----
__device__ float d_sp[3];
__device__ float d_M[FIN * NH];
__device__ float d_bvec[NH];
__device__ unsigned char d_code[NE];   // 0/1/2 -> which softmax weight
__device__ float d_dinv[NN];           // deg, then rsqrt(deg) in place
__device__ float d_g[NN * NH];         // dinv[n] * hW[n]
__device__ float d_acc[NN * NH];       // edge-sum accumulator (init = g, self-loop)
__device__ float d_pooled[NG * NH];

__device__ __forceinline__ void red_add_v4(float* addr, float a, float b, float c, float d) {
    asm volatile("red.global.add.v4.f32 [%0], {%1,%2,%3,%4};"
                 :: "l"(addr), "f"(a), "f"(b), "f"(c), "f"(d) : "memory");
}

// ---- tiny precompute: softmax(msg_weights), fused matrix M = [gcn_W[0]; emb_W @ gcn_W[1:]], bvec ----
__global__ void k_prep(const float* __restrict__ mw, const float* __restrict__ embW,
                       const float* __restrict__ embB, const float* __restrict__ gcnW) {
    int tid = threadIdx.x;
    if (tid == 0) {
        float m = fmaxf(mw[0], fmaxf(mw[1], mw[2]));
        float e0 = expf(mw[0] - m), e1 = expf(mw[1] - m), e2 = expf(mw[2] - m);
        float inv = 1.0f / (e0 + e1 + e2);
        d_sp[0] = e0 * inv; d_sp[1] = e1 * inv; d_sp[2] = e2 * inv;
    }
    for (int idx = tid; idx < FIN * NH; idx += blockDim.x) {
        int i = idx / NH, k = idx % NH;
        float v;
        if (i == 0) {
            v = gcnW[k];
        } else {
            v = 0.f;
            for (int c = 0; c < 63; c++)
                v += embW[(i - 1) * 63 + c] * gcnW[(1 + c) * NH + k];
        }
        d_M[idx] = v;
    }
    if (tid < NH) {
        float v = 0.f;
        for (int c = 0; c < 63; c++) v += embB[c] * gcnW[(1 + c) * NH + tid];
        d_bvec[tid] = v;
    }
}

// ---- scatter edge codes + init dinv to self-loop weight ----
__global__ void k_ew(const int* __restrict__ km, const int* __restrict__ um,
                     const int* __restrict__ om) {
    int t = blockIdx.x * blockDim.x + threadIdx.x;
    if (t < THIRD)          d_code[__ldg(&km[t])] = 0;
    else if (t < 2 * THIRD) d_code[__ldg(&um[t - THIRD])] = 1;
    else if (t < NE)        d_code[__ldg(&om[t - 2 * THIRD])] = 2;
    if (t < NN) d_dinv[t] = 1.0f;
}

// ---- degree accumulate: 4 edges per thread ----
__global__ void k_deg(const int* __restrict__ ei) {
    int t = blockIdx.x * blockDim.x + threadIdx.x;
    float s0 = d_sp[0], s1 = d_sp[1], s2 = d_sp[2];
    int e0 = t * 4;
    if (e0 + 3 < NE) {
        uchar4 cd = __ldg((const uchar4*)(d_code + e0));
        int4 col = __ldg((const int4*)(ei + NE + e0));
        unsigned char cs[4] = {cd.x, cd.y, cd.z, cd.w};
        int cols[4] = {col.x, col.y, col.z, col.w};
#pragma unroll
        for (int j = 0; j < 4; j++) {
            float w = cs[j] == 0 ? s0 : (cs[j] == 1 ? s1 : s2);
            atomicAdd(&d_dinv[cols[j]], w);
        }
    } else {
        for (int e = e0; e < NE; e++) {
            unsigned char cd = d_code[e];
            float w = cd == 0 ? s0 : (cd == 1 ? s1 : s2);
            atomicAdd(&d_dinv[__ldg(&ei[NE + e])], w);
        }
    }
}

// ---- k_g: register-blocked GEMM. Block = 256 threads, 128 nodes.
//      Thread (og = tid&3, np = tid>>2) computes nodes {np, np+64} x outputs [og*8, og*8+8).
//      xs row stride 68 floats: 16B-aligned and bank-conflict-free across np lanes. ----
__global__ void __launch_bounds__(256) k_g(const float* __restrict__ x) {
    __shared__ float xs[GBN * XPAD];
    __shared__ float Ms[FIN * NH];
    __shared__ float Bs[NH];
    int tid = threadIdx.x;

    for (int i = tid; i < FIN * NH / 4; i += 256)
        ((float4*)Ms)[i] = ((const float4*)d_M)[i];
    if (tid < NH) Bs[tid] = d_bvec[tid];

    int base = blockIdx.x * GBN;
    int nvalid = min(GBN, NN - base);

    // stage x tile: 128 rows x 16 float4, coalesced (16 threads per row)
    for (int idx = tid; idx < GBN * 16; idx += 256) {
        int row = idx >> 4, c4 = idx & 15;
        if (row < nvalid) {
            float4 v = __ldg((const float4*)(x + (size_t)(base + row) * FIN) + c4);
            *(float4*)(xs + row * XPAD + c4 * 4) = v;
        }
    }
    // zero pooled (grid covers it: 782 blocks * 256 > 8192)
    int gt = blockIdx.x * 256 + tid;
    if (gt < NG * NH) d_pooled[gt] = 0.f;
    __syncthreads();

    int og = tid & 3;            // output group: 8 outputs
    int np = tid >> 2;           // 0..63
    int n0 = np, n1 = np + 64;
    if (n0 >= nvalid) return;
    bool has1 = (n1 < nvalid);

    float a0[8], a1[8];
#pragma unroll
    for (int k = 0; k < 8; k++) { a0[k] = Bs[og * 8 + k]; a1[k] = a0[k]; }

    const float* x0 = xs + n0 * XPAD;
    const float* x1 = xs + n1 * XPAD;
#pragma unroll
    for (int k4 = 0; k4 < FIN / 4; k4++) {
        float4 xa = *(const float4*)(x0 + k4 * 4);
        float4 xb = has1 ? *(const float4*)(x1 + k4 * 4) : make_float4(0.f, 0.f, 0.f, 0.f);
        float xav[4] = {xa.x, xa.y, xa.z, xa.w};
        float xbv[4] = {xb.x, xb.y, xb.z, xb.w};
#pragma unroll
        for (int j = 0; j < 4; j++) {
            const float4* mrow = (const float4*)(Ms + (k4 * 4 + j) * NH + og * 8);
            float4 m0 = mrow[0], m1 = mrow[1];
            float va = xav[j], vb = xbv[j];
            a0[0] = fmaf(va, m0.x, a0[0]); a1[0] = fmaf(vb, m0.x, a1[0]);
            a0[1] = fmaf(va, m0.y, a0[1]); a1[1] = fmaf(vb, m0.y, a1[1]);
            a0[2] = fmaf(va, m0.z, a0[2]); a1[2] = fmaf(vb, m0.z, a1[2]);
            a0[3] = fmaf(va, m0.w, a0[3]); a1[3] = fmaf(vb, m0.w, a1[3]);
            a0[4] = fmaf(va, m1.x, a0[4]); a1[4] = fmaf(vb, m1.x, a1[4]);
            a0[5] = fmaf(va, m1.y, a0[5]); a1[5] = fmaf(vb, m1.y, a1[5]);
            a0[6] = fmaf(va, m1.z, a0[6]); a1[6] = fmaf(vb, m1.z, a1[6]);
            a0[7] = fmaf(va, m1.w, a0[7]); a1[7] = fmaf(vb, m1.w, a1[7]);
        }
    }

    // all og-lanes for a node are in the same warp: LDG (all) precedes STG (og==0)
    float deg0 = d_dinv[base + n0];
    float di0 = (deg0 > 0.f) ? rsqrtf(deg0) : 0.f;
    float di1 = 0.f;
    if (has1) {
        float deg1 = d_dinv[base + n1];
        di1 = (deg1 > 0.f) ? rsqrtf(deg1) : 0.f;
    }
    if (og == 0) {
        d_dinv[base + n0] = di0;
        if (has1) d_dinv[base + n1] = di1;
    }

    size_t o0 = (size_t)(base + n0) * NH + og * 8;
    float4 v00, v01;
    v00.x = di0 * a0[0]; v00.y = di0 * a0[1]; v00.z = di0 * a0[2]; v00.w = di0 * a0[3];
    v01.x = di0 * a0[4]; v01.y = di0 * a0[5]; v01.z = di0 * a0[6]; v01.w = di0 * a0[7];
    *(float4*)(d_g + o0) = v00; *(float4*)(d_g + o0 + 4) = v01;
    *(float4*)(d_acc + o0) = v00; *(float4*)(d_acc + o0 + 4) = v01;
    if (has1) {
        size_t o1 = (size_t)(base + n1) * NH + og * 8;
        float4 v10, v11;
        v10.x = di1 * a1[0]; v10.y = di1 * a1[1]; v10.z = di1 * a1[2]; v10.w = di1 * a1[3];
        v11.x = di1 * a1[4]; v11.y = di1 * a1[5]; v11.z = di1 * a1[6]; v11.w = di1 * a1[7];
        *(float4*)(d_g + o1) = v10; *(float4*)(d_g + o1 + 4) = v11;
        *(float4*)(d_acc + o1) = v10; *(float4*)(d_acc + o1 + 4) = v11;
    }
}

// ---- hot loop: 8 threads per edge, float4 gather + red.global.add.v4.f32 ----
__global__ void k_edge(const int* __restrict__ ei) {
    int tid = blockIdx.x * blockDim.x + threadIdx.x;
    int quad = tid & 7;             // which float4 of the 32-feature row
    int eidx = tid >> 3;
    int estride = (gridDim.x * blockDim.x) >> 3;
    float s0 = d_sp[0], s1 = d_sp[1], s2 = d_sp[2];
    for (int e = eidx; e < NE; e += estride) {
        int r = __ldg(&ei[e]);
        int c = __ldg(&ei[NE + e]);
        unsigned char cd = __ldg(&d_code[e]);
        float w = cd == 0 ? s0 : (cd == 1 ? s1 : s2);
        float4 gv = __ldg((const float4*)(d_g + (size_t)r * NH) + quad);
        red_add_v4(d_acc + (size_t)c * NH + quad * 4,
                   w * gv.x, w * gv.y, w * gv.z, w * gv.w);
    }
}

// ---- fixup + relu + segment pool (batch sorted -> register accumulation per warp) ----
#define CHUNK 16
__global__ void k_pool(const int* __restrict__ batch, const float* __restrict__ gcnB) {
    int lane = threadIdx.x & 31;
    int warp = (blockIdx.x * blockDim.x + threadIdx.x) >> 5;
    int start = warp * CHUNK;
    if (start >= NN) return;
    int end = min(start + CHUNK, NN);
    float gb = __ldg(&gcnB[lane]);
    int cur = __ldg(&batch[start]);
    float accr = 0.f;
    for (int n = start; n < end; n++) {
        int b = __ldg(&batch[n]);
        if (b != cur) {
            atomicAdd(&d_pooled[cur * NH + lane], accr);
            accr = 0.f;
            cur = b;
        }
        float a = __ldg(&d_acc[(size_t)n * NH + lane]);   // includes self-loop g
        float v = fmaxf(fmaf(d_dinv[n], a, gb), 0.f);
        accr += v;
    }
    atomicAdd(&d_pooled[cur * NH + lane], accr);
}

// ---- head MLP: one thread per graph ----
__global__ void k_final(const float* __restrict__ fc1W, const float* __restrict__ fc1B,
                        const float* __restrict__ outW, const float* __restrict__ outB,
                        float* __restrict__ out) {
    __shared__ float W[NH * NH], b1[NH], wo[NH];
    int tid = threadIdx.x;
    for (int i = tid; i < NH * NH; i += blockDim.x) W[i] = fc1W[i];
    if (tid < NH) { b1[tid] = fc1B[tid]; wo[tid] = outW[tid]; }
    __syncthreads();
    if (tid >= NG) return;

    float p[NH];
    const float4* pr = (const float4*)(d_pooled + tid * NH);
#pragma unroll
    for (int k4 = 0; k4 < NH / 4; k4++) {
        float4 v = pr[k4];
        p[k4 * 4 + 0] = v.x; p[k4 * 4 + 1] = v.y;
        p[k4 * 4 + 2] = v.z; p[k4 * 4 + 3] = v.w;
    }
    float o = outB[0];
#pragma unroll
    for (int j = 0; j < NH; j++) {
        float z = b1[j];
#pragma unroll
        for (int i = 0; i < NH; i++) z = fmaf(p[i], W[i * NH + j], z);
        o = fmaf(fmaxf(z, 0.f), wo[j], o);
    }
    out[tid] = o;
}

extern "C" void kernel_launch(void* const* d_in, const int* in_sizes, int n_in,
                              void* d_out, int out_size) {
    const float* x    = (const float*)d_in[0];
    const int*   ei   = (const int*)d_in[1];
    const int*   bat  = (const int*)d_in[2];
    const int*   km   = (const int*)d_in[3];
    const int*   um   = (const int*)d_in[4];
    const int*   om   = (const int*)d_in[5];
    const float* mw   = (const float*)d_in[6];
    const float* embW = (const float*)d_in[7];
    const float* embB = (const float*)d_in[8];
    const float* gcnW = (const float*)d_in[9];
    const float* gcnB = (const float*)d_in[10];
    const float* fc1W = (const float*)d_in[11];
    const float* fc1B = (const float*)d_in[12];
    const float* outW = (const float*)d_in[13];
    const float* outB = (const float*)d_in[14];
    float* out = (float*)d_out;

    k_prep<<<1, 256>>>(mw, embW, embB, gcnW);
    k_ew<<<(NE + 255) / 256, 256>>>(km, um, om);
    k_deg<<<(NE / 4 + 255) / 256, 256>>>(ei);
    k_g<<<(NN + GBN - 1) / GBN, 256>>>(x);
    k_edge<<<2368, 256>>>(ei);
    int pool_warps = (NN + CHUNK - 1) / CHUNK;
    k_pool<<<(pool_warps + 7) / 8, 256>>>(bat, gcnB);
    k_final<<<1, 256>>>(fc1W, fc1B, outW, outB, out);
}

// round 7
// speedup vs baseline: 1.0212x; 1.0212x over previous
#include <cuda_runtime.h>

#define NN 100000
#define NE 3000000
#define THIRD (NE/3)
#define NG 256
#define FIN 64
#define NH 32

#define GBN 64           // nodes per block in k_g (small tile -> high occupancy)
#define XPAD 68          // padded row stride (272B: 16B-aligned, conflict-free)

// ---- scratch (no allocations allowed) ----
__device__ float d_sp[3];
__device__ float d_M[FIN * NH];
__device__ float d_bvec[NH];
__device__ unsigned char d_code[NE];   // 0/1/2 -> which softmax weight
__device__ float d_dinv[NN];           // deg, then rsqrt(deg) in place
__device__ float d_g[NN * NH];         // dinv[n] * hW[n]
__device__ float d_acc[NN * NH];       // edge-sum accumulator (init = g, self-loop)
__device__ float d_pooled[NG * NH];

__device__ __forceinline__ void red_add_v4(float* addr, float a, float b, float c, float d) {
    asm volatile("red.global.add.v4.f32 [%0], {%1,%2,%3,%4};"
                 :: "l"(addr), "f"(a), "f"(b), "f"(c), "f"(d) : "memory");
}

// ---- tiny precompute: softmax(msg_weights), fused matrix M = [gcn_W[0]; emb_W @ gcn_W[1:]], bvec ----
__global__ void k_prep(const float* __restrict__ mw, const float* __restrict__ embW,
                       const float* __restrict__ embB, const float* __restrict__ gcnW) {
    int tid = threadIdx.x;
    if (tid == 0) {
        float m = fmaxf(mw[0], fmaxf(mw[1], mw[2]));
        float e0 = expf(mw[0] - m), e1 = expf(mw[1] - m), e2 = expf(mw[2] - m);
        float inv = 1.0f / (e0 + e1 + e2);
        d_sp[0] = e0 * inv; d_sp[1] = e1 * inv; d_sp[2] = e2 * inv;
    }
    for (int idx = tid; idx < FIN * NH; idx += blockDim.x) {
        int i = idx / NH, k = idx % NH;
        float v;
        if (i == 0) {
            v = gcnW[k];
        } else {
            v = 0.f;
            for (int c = 0; c < 63; c++)
                v += embW[(i - 1) * 63 + c] * gcnW[(1 + c) * NH + k];
        }
        d_M[idx] = v;
    }
    if (tid < NH) {
        float v = 0.f;
        for (int c = 0; c < 63; c++) v += embB[c] * gcnW[(1 + c) * NH + tid];
        d_bvec[tid] = v;
    }
}

// ---- scatter edge codes + init dinv to self-loop weight ----
__global__ void k_ew(const int* __restrict__ km, const int* __restrict__ um,
                     const int* __restrict__ om) {
    int t = blockIdx.x * blockDim.x + threadIdx.x;
    if (t < THIRD)          d_code[__ldg(&km[t])] = 0;
    else if (t < 2 * THIRD) d_code[__ldg(&um[t - THIRD])] = 1;
    else if (t < NE)        d_code[__ldg(&om[t - 2 * THIRD])] = 2;
    if (t < NN) d_dinv[t] = 1.0f;
}

// ---- degree accumulate: 4 edges per thread ----
__global__ void k_deg(const int* __restrict__ ei) {
    int t = blockIdx.x * blockDim.x + threadIdx.x;
    float s0 = d_sp[0], s1 = d_sp[1], s2 = d_sp[2];
    int e0 = t * 4;
    if (e0 + 3 < NE) {
        uchar4 cd = __ldg((const uchar4*)(d_code + e0));
        int4 col = __ldg((const int4*)(ei + NE + e0));
        unsigned char cs[4] = {cd.x, cd.y, cd.z, cd.w};
        int cols[4] = {col.x, col.y, col.z, col.w};
#pragma unroll
        for (int j = 0; j < 4; j++) {
            float w = cs[j] == 0 ? s0 : (cs[j] == 1 ? s1 : s2);
            atomicAdd(&d_dinv[cols[j]], w);
        }
    } else {
        for (int e = e0; e < NE; e++) {
            unsigned char cd = d_code[e];
            float w = cd == 0 ? s0 : (cd == 1 ? s1 : s2);
            atomicAdd(&d_dinv[__ldg(&ei[NE + e])], w);
        }
    }
}

// ---- k_g: 256 threads = 64 nodes/block, thread (og, np) = node np x outputs [og*8, og*8+8).
//      Small tile -> 8 resident blocks/SM -> deep LDG pipeline on the x stream. ----
__global__ void __launch_bounds__(256) k_g(const float* __restrict__ x) {
    __shared__ float xs[GBN * XPAD];
    __shared__ float Ms[FIN * NH];
    __shared__ float Bs[NH];
    int tid = threadIdx.x;

    for (int i = tid; i < FIN * NH / 4; i += 256)
        ((float4*)Ms)[i] = ((const float4*)d_M)[i];
    if (tid < NH) Bs[tid] = d_bvec[tid];

    int base = blockIdx.x * GBN;
    int nvalid = min(GBN, NN - base);

    // stage x tile: 64 rows x 16 float4, coalesced (16 threads per row), 4 per thread
    for (int idx = tid; idx < GBN * 16; idx += 256) {
        int row = idx >> 4, c4 = idx & 15;
        if (row < nvalid) {
            float4 v = __ldg((const float4*)(x + (size_t)(base + row) * FIN) + c4);
            *(float4*)(xs + row * XPAD + c4 * 4) = v;
        }
    }
    // zero pooled (1563 blocks * 256 covers 8192)
    int gt = blockIdx.x * 256 + tid;
    if (gt < NG * NH) d_pooled[gt] = 0.f;
    __syncthreads();

    int og = tid & 3;            // output group: 8 outputs
    int np = tid >> 2;           // node 0..63
    if (np >= nvalid) return;

    float a0[8];
#pragma unroll
    for (int k = 0; k < 8; k++) a0[k] = Bs[og * 8 + k];

    const float* x0 = xs + np * XPAD;
#pragma unroll
    for (int k4 = 0; k4 < FIN / 4; k4++) {
        float4 xa = *(const float4*)(x0 + k4 * 4);
        float xav[4] = {xa.x, xa.y, xa.z, xa.w};
#pragma unroll
        for (int j = 0; j < 4; j++) {
            const float4* mrow = (const float4*)(Ms + (k4 * 4 + j) * NH + og * 8);
            float4 m0 = mrow[0], m1 = mrow[1];
            float va = xav[j];
            a0[0] = fmaf(va, m0.x, a0[0]);
            a0[1] = fmaf(va, m0.y, a0[1]);
            a0[2] = fmaf(va, m0.z, a0[2]);
            a0[3] = fmaf(va, m0.w, a0[3]);
            a0[4] = fmaf(va, m1.x, a0[4]);
            a0[5] = fmaf(va, m1.y, a0[5]);
            a0[6] = fmaf(va, m1.z, a0[6]);
            a0[7] = fmaf(va, m1.w, a0[7]);
        }
    }

    // all og-lanes for a node are in the same warp: LDG (all) precedes STG (og==0)
    float deg0 = d_dinv[base + np];
    float di0 = (deg0 > 0.f) ? rsqrtf(deg0) : 0.f;
    if (og == 0) d_dinv[base + np] = di0;

    size_t o0 = (size_t)(base + np) * NH + og * 8;
    float4 v00, v01;
    v00.x = di0 * a0[0]; v00.y = di0 * a0[1]; v00.z = di0 * a0[2]; v00.w = di0 * a0[3];
    v01.x = di0 * a0[4]; v01.y = di0 * a0[5]; v01.z = di0 * a0[6]; v01.w = di0 * a0[7];
    *(float4*)(d_g + o0) = v00; *(float4*)(d_g + o0 + 4) = v01;
    *(float4*)(d_acc + o0) = v00; *(float4*)(d_acc + o0 + 4) = v01;
}

// ---- hot loop: 8 threads per edge, float4 gather + red.global.add.v4.f32 ----
__global__ void k_edge(const int* __restrict__ ei) {
    int tid = blockIdx.x * blockDim.x + threadIdx.x;
    int quad = tid & 7;             // which float4 of the 32-feature row
    int eidx = tid >> 3;
    int estride = (gridDim.x * blockDim.x) >> 3;
    float s0 = d_sp[0], s1 = d_sp[1], s2 = d_sp[2];
    for (int e = eidx; e < NE; e += estride) {
        int r = __ldg(&ei[e]);
        int c = __ldg(&ei[NE + e]);
        unsigned char cd = __ldg(&d_code[e]);
        float w = cd == 0 ? s0 : (cd == 1 ? s1 : s2);
        float4 gv = __ldg((const float4*)(d_g + (size_t)r * NH) + quad);
        red_add_v4(d_acc + (size_t)c * NH + quad * 4,
                   w * gv.x, w * gv.y, w * gv.z, w * gv.w);
    }
}

// ---- fixup + relu + segment pool (batch sorted -> register accumulation per warp) ----
#define CHUNK 16
__global__ void k_pool(const int* __restrict__ batch, const float* __restrict__ gcnB) {
    int lane = threadIdx.x & 31;
    int warp = (blockIdx.x * blockDim.x + threadIdx.x) >> 5;
    int start = warp * CHUNK;
    if (start >= NN) return;
    int end = min(start + CHUNK, NN);
    float gb = __ldg(&gcnB[lane]);
    int cur = __ldg(&batch[start]);
    float accr = 0.f;
    for (int n = start; n < end; n++) {
        int b = __ldg(&batch[n]);
        if (b != cur) {
            atomicAdd(&d_pooled[cur * NH + lane], accr);
            accr = 0.f;
            cur = b;
        }
        float a = __ldg(&d_acc[(size_t)n * NH + lane]);   // includes self-loop g
        float v = fmaxf(fmaf(d_dinv[n], a, gb), 0.f);
        accr += v;
    }
    atomicAdd(&d_pooled[cur * NH + lane], accr);
}

// ---- head MLP: one thread per graph ----
__global__ void k_final(const float* __restrict__ fc1W, const float* __restrict__ fc1B,
                        const float* __restrict__ outW, const float* __restrict__ outB,
                        float* __restrict__ out) {
    __shared__ float W[NH * NH], b1[NH], wo[NH];
    int tid = threadIdx.x;
    for (int i = tid; i < NH * NH; i += blockDim.x) W[i] = fc1W[i];
    if (tid < NH) { b1[tid] = fc1B[tid]; wo[tid] = outW[tid]; }
    __syncthreads();
    if (tid >= NG) return;

    float p[NH];
    const float4* pr = (const float4*)(d_pooled + tid * NH);
#pragma unroll
    for (int k4 = 0; k4 < NH / 4; k4++) {
        float4 v = pr[k4];
        p[k4 * 4 + 0] = v.x; p[k4 * 4 + 1] = v.y;
        p[k4 * 4 + 2] = v.z; p[k4 * 4 + 3] = v.w;
    }
    float o = outB[0];
#pragma unroll
    for (int j = 0; j < NH; j++) {
        float z = b1[j];
#pragma unroll
        for (int i = 0; i < NH; i++) z = fmaf(p[i], W[i * NH + j], z);
        o = fmaf(fmaxf(z, 0.f), wo[j], o);
    }
    out[tid] = o;
}

extern "C" void kernel_launch(void* const* d_in, const int* in_sizes, int n_in,
                              void* d_out, int out_size) {
    const float* x    = (const float*)d_in[0];
    const int*   ei   = (const int*)d_in[1];
    const int*   bat  = (const int*)d_in[2];
    const int*   km   = (const int*)d_in[3];
    const int*   um   = (const int*)d_in[4];
    const int*   om   = (const int*)d_in[5];
    const float* mw   = (const float*)d_in[6];
    const float* embW = (const float*)d_in[7];
    const float* embB = (const float*)d_in[8];
    const float* gcnW = (const float*)d_in[9];
    const float* gcnB = (const float*)d_in[10];
    const float* fc1W = (const float*)d_in[11];
    const float* fc1B = (const float*)d_in[12];
    const float* outW = (const float*)d_in[13];
    const float* outB = (const float*)d_in[14];
    float* out = (float*)d_out;

    k_prep<<<1, 256>>>(mw, embW, embB, gcnW);
    k_ew<<<(NE + 255) / 256, 256>>>(km, um, om);
    k_deg<<<(NE / 4 + 255) / 256, 256>>>(ei);
    k_g<<<(NN + GBN - 1) / GBN, 256>>>(x);
    k_edge<<<2368, 256>>>(ei);
    int pool_warps = (NN + CHUNK - 1) / CHUNK;
    k_pool<<<(pool_warps + 7) / 8, 256>>>(bat, gcnB);
    k_final<<<1, 256>>>(fc1W, fc1B, outW, outB, out);
}

// round 9
// speedup vs baseline: 1.0241x; 1.0028x over previous
#include <cuda_runtime.h>
#include <cuda_bf16.h>

#define NN 100000
#define NE 3000000
#define THIRD (NE/3)
#define NG 256
#define FIN 64
#define NH 32

#define GBN 64           // nodes per block in k_g
#define XPAD 68          // padded row stride (272B: 16B-aligned, conflict-free)

// ---- scratch (no allocations allowed) ----
__device__ float d_sp[3];
__device__ float d_M[FIN * NH];
__device__ float d_bvec[NH];
__device__ unsigned char d_code[NE];        // 0/1/2 -> which softmax weight
__device__ float d_dinv[NN];                // deg, then rsqrt(deg) in place
__device__ __nv_bfloat162 d_gh[NN * NH / 2]; // bf16 copy of g for the edge gather
__device__ float d_acc[NN * NH];            // fp32 edge-sum accumulator (seeded with g)
__device__ float d_pooled[NG * NH];

__device__ __forceinline__ void red_add_v4(float* addr, float a, float b, float c, float d) {
    asm volatile("red.global.add.v4.f32 [%0], {%1,%2,%3,%4};"
                 :: "l"(addr), "f"(a), "f"(b), "f"(c), "f"(d) : "memory");
}

// ---- tiny precompute: softmax(msg_weights), fused matrix M = [gcn_W[0]; emb_W @ gcn_W[1:]], bvec ----
__global__ void k_prep(const float* __restrict__ mw, const float* __restrict__ embW,
                       const float* __restrict__ embB, const float* __restrict__ gcnW) {
    int tid = threadIdx.x;
    if (tid == 0) {
        float m = fmaxf(mw[0], fmaxf(mw[1], mw[2]));
        float e0 = expf(mw[0] - m), e1 = expf(mw[1] - m), e2 = expf(mw[2] - m);
        float inv = 1.0f / (e0 + e1 + e2);
        d_sp[0] = e0 * inv; d_sp[1] = e1 * inv; d_sp[2] = e2 * inv;
    }
    for (int idx = tid; idx < FIN * NH; idx += blockDim.x) {
        int i = idx / NH, k = idx % NH;
        float v;
        if (i == 0) {
            v = gcnW[k];
        } else {
            v = 0.f;
            for (int c = 0; c < 63; c++)
                v += embW[(i - 1) * 63 + c] * gcnW[(1 + c) * NH + k];
        }
        d_M[idx] = v;
    }
    if (tid < NH) {
        float v = 0.f;
        for (int c = 0; c < 63; c++) v += embB[c] * gcnW[(1 + c) * NH + tid];
        d_bvec[tid] = v;
    }
}

// ---- scatter edge codes + init dinv to self-loop weight ----
__global__ void k_ew(const int* __restrict__ km, const int* __restrict__ um,
                     const int* __restrict__ om) {
    int t = blockIdx.x * blockDim.x + threadIdx.x;
    if (t < THIRD)          d_code[__ldg(&km[t])] = 0;
    else if (t < 2 * THIRD) d_code[__ldg(&um[t - THIRD])] = 1;
    else if (t < NE)        d_code[__ldg(&om[t - 2 * THIRD])] = 2;
    if (t < NN) d_dinv[t] = 1.0f;
}

// ---- degree accumulate: 4 edges per thread ----
__global__ void k_deg(const int* __restrict__ ei) {
    int t = blockIdx.x * blockDim.x + threadIdx.x;
    float s0 = d_sp[0], s1 = d_sp[1], s2 = d_sp[2];
    int e0 = t * 4;
    if (e0 + 3 < NE) {
        uchar4 cd = __ldg((const uchar4*)(d_code + e0));
        int4 col = __ldg((const int4*)(ei + NE + e0));
        unsigned char cs[4] = {cd.x, cd.y, cd.z, cd.w};
        int cols[4] = {col.x, col.y, col.z, col.w};
#pragma unroll
        for (int j = 0; j < 4; j++) {
            float w = cs[j] == 0 ? s0 : (cs[j] == 1 ? s1 : s2);
            atomicAdd(&d_dinv[cols[j]], w);
        }
    } else {
        for (int e = e0; e < NE; e++) {
            unsigned char cd = d_code[e];
            float w = cd == 0 ? s0 : (cd == 1 ? s1 : s2);
            atomicAdd(&d_dinv[__ldg(&ei[NE + e])], w);
        }
    }
}

// ---- k_g: 256 threads = 64 nodes/block, thread (og, np) = node np x outputs [og*8, og*8+8).
//      Writes fp32 seed into d_acc and bf16 copy into d_gh for the gather. ----
__global__ void __launch_bounds__(256) k_g(const float* __restrict__ x) {
    __shared__ float xs[GBN * XPAD];
    __shared__ float Ms[FIN * NH];
    __shared__ float Bs[NH];
    int tid = threadIdx.x;

    for (int i = tid; i < FIN * NH / 4; i += 256)
        ((float4*)Ms)[i] = ((const float4*)d_M)[i];
    if (tid < NH) Bs[tid] = d_bvec[tid];

    int base = blockIdx.x * GBN;
    int nvalid = min(GBN, NN - base);

    for (int idx = tid; idx < GBN * 16; idx += 256) {
        int row = idx >> 4, c4 = idx & 15;
        if (row < nvalid) {
            float4 v = __ldg((const float4*)(x + (size_t)(base + row) * FIN) + c4);
            *(float4*)(xs + row * XPAD + c4 * 4) = v;
        }
    }
    int gt = blockIdx.x * 256 + tid;
    if (gt < NG * NH) d_pooled[gt] = 0.f;
    __syncthreads();

    int og = tid & 3;            // output group: 8 outputs
    int np = tid >> 2;           // node 0..63
    if (np >= nvalid) return;

    float a0[8];
#pragma unroll
    for (int k = 0; k < 8; k++) a0[k] = Bs[og * 8 + k];

    const float* x0 = xs + np * XPAD;
#pragma unroll
    for (int k4 = 0; k4 < FIN / 4; k4++) {
        float4 xa = *(const float4*)(x0 + k4 * 4);
        float xav[4] = {xa.x, xa.y, xa.z, xa.w};
#pragma unroll
        for (int j = 0; j < 4; j++) {
            const float4* mrow = (const float4*)(Ms + (k4 * 4 + j) * NH + og * 8);
            float4 m0 = mrow[0], m1 = mrow[1];
            float va = xav[j];
            a0[0] = fmaf(va, m0.x, a0[0]);
            a0[1] = fmaf(va, m0.y, a0[1]);
            a0[2] = fmaf(va, m0.z, a0[2]);
            a0[3] = fmaf(va, m0.w, a0[3]);
            a0[4] = fmaf(va, m1.x, a0[4]);
            a0[5] = fmaf(va, m1.y, a0[5]);
            a0[6] = fmaf(va, m1.z, a0[6]);
            a0[7] = fmaf(va, m1.w, a0[7]);
        }
    }

    float deg0 = d_dinv[base + np];
    float di0 = (deg0 > 0.f) ? rsqrtf(deg0) : 0.f;
    if (og == 0) d_dinv[base + np] = di0;

    float r0 = di0 * a0[0], r1 = di0 * a0[1], r2 = di0 * a0[2], r3 = di0 * a0[3];
    float r4 = di0 * a0[4], r5 = di0 * a0[5], r6 = di0 * a0[6], r7 = di0 * a0[7];

    size_t o0 = (size_t)(base + np) * NH + og * 8;
    *(float4*)(d_acc + o0)     = make_float4(r0, r1, r2, r3);
    *(float4*)(d_acc + o0 + 4) = make_float4(r4, r5, r6, r7);

    // bf16 copy: 8 values = 4 x bf162 = 16B
    __nv_bfloat162 h0 = __floats2bfloat162_rn(r0, r1);
    __nv_bfloat162 h1 = __floats2bfloat162_rn(r2, r3);
    __nv_bfloat162 h2 = __floats2bfloat162_rn(r4, r5);
    __nv_bfloat162 h3 = __floats2bfloat162_rn(r6, r7);
    uint4 packed;
    packed.x = *(unsigned int*)&h0;
    packed.y = *(unsigned int*)&h1;
    packed.z = *(unsigned int*)&h2;
    packed.w = *(unsigned int*)&h3;
    *(uint4*)((__nv_bfloat16*)d_gh + (size_t)(base + np) * NH + og * 8) = packed;
}

// ---- hot loop: 8 threads per edge, bf16 8B gather + fp32 red.global.add.v4 ----
__global__ void k_edge(const int* __restrict__ ei) {
    int tid = blockIdx.x * blockDim.x + threadIdx.x;
    int quad = tid & 7;             // which 4-feature slice of the 32-feature row
    int eidx = tid >> 3;
    int estride = (gridDim.x * blockDim.x) >> 3;
    float s0 = d_sp[0], s1 = d_sp[1], s2 = d_sp[2];
    for (int e = eidx; e < NE; e += estride) {
        int r = __ldg(&ei[e]);
        int c = __ldg(&ei[NE + e]);
        unsigned char cd = __ldg(&d_code[e]);
        float w = cd == 0 ? s0 : (cd == 1 ? s1 : s2);
        uint2 raw = __ldg((const uint2*)(d_gh + (size_t)r * (NH / 2) + quad * 2));
        __nv_bfloat162 b0 = *(__nv_bfloat162*)&raw.x;
        __nv_bfloat162 b1 = *(__nv_bfloat162*)&raw.y;
        float2 f0 = __bfloat1622float2(b0);
        float2 f1 = __bfloat1622float2(b1);
        red_add_v4(d_acc + (size_t)c * NH + quad * 4,
                   w * f0.x, w * f0.y, w * f1.x, w * f1.y);
    }
}

// ---- fixup + relu + segment pool (batch sorted -> register accumulation per warp) ----
#define CHUNK 16
__global__ void k_pool(const int* __restrict__ batch, const float* __restrict__ gcnB) {
    int lane = threadIdx.x & 31;
    int warp = (blockIdx.x * blockDim.x + threadIdx.x) >> 5;
    int start = warp * CHUNK;
    if (start >= NN) return;
    int end = min(start + CHUNK, NN);
    float gb = __ldg(&gcnB[lane]);
    int cur = __ldg(&batch[start]);
    float accr = 0.f;
    for (int n = start; n < end; n++) {
        int b = __ldg(&batch[n]);
        if (b != cur) {
            atomicAdd(&d_pooled[cur * NH + lane], accr);
            accr = 0.f;
            cur = b;
        }
        float a = __ldg(&d_acc[(size_t)n * NH + lane]);   // includes self-loop g (fp32)
        float v = fmaxf(fmaf(d_dinv[n], a, gb), 0.f);
        accr += v;
    }
    atomicAdd(&d_pooled[cur * NH + lane], accr);
}

// ---- head MLP: one thread per graph ----
__global__ void k_final(const float* __restrict__ fc1W, const float* __restrict__ fc1B,
                        const float* __restrict__ outW, const float* __restrict__ outB,
                        float* __restrict__ out) {
    __shared__ float W[NH * NH], b1[NH], wo[NH];
    int tid = threadIdx.x;
    for (int i = tid; i < NH * NH; i += blockDim.x) W[i] = fc1W[i];
    if (tid < NH) { b1[tid] = fc1B[tid]; wo[tid] = outW[tid]; }
    __syncthreads();
    if (tid >= NG) return;

    float p[NH];
    const float4* pr = (const float4*)(d_pooled + tid * NH);
#pragma unroll
    for (int k4 = 0; k4 < NH / 4; k4++) {
        float4 v = pr[k4];
        p[k4 * 4 + 0] = v.x; p[k4 * 4 + 1] = v.y;
        p[k4 * 4 + 2] = v.z; p[k4 * 4 + 3] = v.w;
    }
    float o = outB[0];
#pragma unroll
    for (int j = 0; j < NH; j++) {
        float z = b1[j];
#pragma unroll
        for (int i = 0; i < NH; i++) z = fmaf(p[i], W[i * NH + j], z);
        o = fmaf(fmaxf(z, 0.f), wo[j], o);
    }
    out[tid] = o;
}

extern "C" void kernel_launch(void* const* d_in, const int* in_sizes, int n_in,
                              void* d_out, int out_size) {
    const float* x    = (const float*)d_in[0];
    const int*   ei   = (const int*)d_in[1];
    const int*   bat  = (const int*)d_in[2];
    const int*   km   = (const int*)d_in[3];
    const int*   um   = (const int*)d_in[4];
    const int*   om   = (const int*)d_in[5];
    const float* mw   = (const float*)d_in[6];
    const float* embW = (const float*)d_in[7];
    const float* embB = (const float*)d_in[8];
    const float* gcnW = (const float*)d_in[9];
    const float* gcnB = (const float*)d_in[10];
    const float* fc1W = (const float*)d_in[11];
    const float* fc1B = (const float*)d_in[12];
    const float* outW = (const float*)d_in[13];
    const float* outB = (const float*)d_in[14];
    float* out = (float*)d_out;

    k_prep<<<1, 256>>>(mw, embW, embB, gcnW);
    k_ew<<<(NE + 255) / 256, 256>>>(km, um, om);
    k_deg<<<(NE / 4 + 255) / 256, 256>>>(ei);
    k_g<<<(NN + GBN - 1) / GBN, 256>>>(x);
    k_edge<<<2368, 256>>>(ei);
    int pool_warps = (NN + CHUNK - 1) / CHUNK;
    k_pool<<<(pool_warps + 7) / 8, 256>>>(bat, gcnB);
    k_final<<<1, 256>>>(fc1W, fc1B, outW, outB, out);
}